// round 2
// baseline (speedup 1.0000x reference)
#include <cuda_runtime.h>
#include <math.h>

#define BATCH 4
#define C 64
#define HH 256
#define WW 256
#define NPIX (HH*WW)
#define NHEADS 8
#define HD 8
#define NCHUNK 64
#define CHUNK (NPIX/NCHUNK)   // 1024

// ---------------- scratch (static device globals; no allocations) ----------------
__device__ float g_mid[BATCH*C*NPIX];         // conv1x1 staging (reused 3x)
__device__ float g_Q[BATCH*C*NPIX];
__device__ float g_K[BATCH*C*NPIX];
__device__ float g_V[BATCH*C*NPIX];
__device__ float g_part[BATCH*NHEADS*NCHUNK*80];
__device__ float g_attn[BATCH*NHEADS*HD*HD];
__device__ float g_weff[BATCH*C*C];

// ---------------- packed f32x2 helpers ----------------
__device__ __forceinline__ unsigned long long pack2(float lo, float hi) {
    unsigned long long r;
    asm("mov.b64 %0, {%1,%2};" : "=l"(r)
        : "r"(__float_as_uint(lo)), "r"(__float_as_uint(hi)));
    return r;
}
__device__ __forceinline__ void unpack2(unsigned long long p, float& lo, float& hi) {
    unsigned int a, b;
    asm("mov.b64 {%0,%1}, %2;" : "=r"(a), "=r"(b) : "l"(p));
    lo = __uint_as_float(a); hi = __uint_as_float(b);
}
#define FMA2(acc, a, b) \
    asm("fma.rn.f32x2 %0, %1, %2, %0;" : "+l"(acc) : "l"(a), "l"(b))

// ---------------- conv1x1: out[co][pix] = sum_ci w[co][ci] * in[ci][pix] ------
// 256 threads, 1 pixel/thread, 64 fp32 acc as 32 packed u64. Weights staged in
// smem as (co-pair, ci) u64 so inner loop is LDS.128 broadcast + FFMA2.
__global__ void __launch_bounds__(256) conv1x1_64(
    const float* __restrict__ in, const float* __restrict__ w,
    float* __restrict__ out)
{
    __shared__ unsigned long long s_wp[C*32];   // [ci][co-pair]
    const int tid = threadIdx.x;
    const int b = blockIdx.y;
    const int n = blockIdx.x*256 + tid;

    for (int idx = tid; idx < C*32; idx += 256) {
        const int ci = idx >> 5, p = idx & 31;
        s_wp[idx] = pack2(w[(2*p)*C + ci], w[(2*p+1)*C + ci]);
    }
    __syncthreads();

    const float* ib = in + (size_t)b*(C*NPIX);
    unsigned long long acc[32];
    #pragma unroll
    for (int q = 0; q < 32; q++) acc[q] = 0ULL;
    #pragma unroll 4
    for (int ci = 0; ci < C; ci++) {
        const float v = __ldg(ib + ci*NPIX + n);
        const unsigned long long vv = pack2(v, v);
        const ulonglong2* wr = (const ulonglong2*)(s_wp + ci*32);
        #pragma unroll
        for (int q = 0; q < 16; q++) {
            const ulonglong2 wq = wr[q];
            FMA2(acc[2*q],   vv, wq.x);
            FMA2(acc[2*q+1], vv, wq.y);
        }
    }
    float* ob = out + (size_t)b*(C*NPIX);
    #pragma unroll
    for (int q = 0; q < 32; q++) {
        float lo, hi; unpack2(acc[q], lo, hi);
        ob[(2*q)*NPIX + n]   = lo;
        ob[(2*q+1)*NPIX + n] = hi;
    }
}

// ---------------- depthwise 3x3, pad=1 ----------------------------------------
// grid (WW/32, HH/8, BATCH*C); block 256 = 32x8. Pure memory, L1 serves stencil.
__global__ void __launch_bounds__(256) dw3x3(
    const float* __restrict__ in, const float* __restrict__ w,
    float* __restrict__ out)
{
    const int z = blockIdx.z;                       // b*C + c
    const float* ib = in + (size_t)z*NPIX;
    float* ob = out + (size_t)z*NPIX;
    const float* wc = w + (z & (C-1))*9;

    const int tid = threadIdx.x;
    const int x = blockIdx.x*32 + (tid & 31);
    const int y = blockIdx.y*8  + (tid >> 5);

    float wr[9];
    #pragma unroll
    for (int i = 0; i < 9; i++) wr[i] = __ldg(wc + i);

    float acc = 0.f;
    #pragma unroll
    for (int dy = -1; dy <= 1; dy++) {
        const int yy = y + dy;
        if (yy < 0 || yy >= HH) continue;
        #pragma unroll
        for (int dx = -1; dx <= 1; dx++) {
            const int xx = x + dx;
            if (xx < 0 || xx >= WW) continue;
            acc += wr[(dy+1)*3 + (dx+1)] * __ldg(ib + yy*WW + xx);
        }
    }
    ob[y*WW + x] = acc;
}

// ---------------- attn partial: q.k dots + sum-of-squares ---------------------
// Parity split: even/odd thread pair shares a pixel; even owns q-ch 0-3, odd
// 4-7; both read all 8 k. S shrinks to 32 regs -> ~75 regs total, 3 CTAs/SM.
__global__ void __launch_bounds__(256) attn_partial()
{
    const int chunk = blockIdx.x, h = blockIdx.y, b = blockIdx.z;
    const int tid = threadIdx.x;
    const int parity = tid & 1, slot = tid >> 1;    // 128 pixel-slots/iter
    const float* qb = g_Q + (size_t)(b*C + h*HD) * NPIX + parity*4*NPIX;
    const float* kb = g_K + (size_t)(b*C + h*HD) * NPIX;

    float S[32], qs[4], ks[8];
    #pragma unroll
    for (int i = 0; i < 32; i++) S[i] = 0.f;
    #pragma unroll
    for (int i = 0; i < 4; i++) qs[i] = 0.f;
    #pragma unroll
    for (int i = 0; i < 8; i++) ks[i] = 0.f;

    const int n0 = chunk * CHUNK;
    #pragma unroll 2
    for (int it = 0; it < CHUNK/128; it++) {
        const int n = n0 + it*128 + slot;
        float qv[4], kv[8];
        #pragma unroll
        for (int j = 0; j < 4; j++) qv[j] = qb[j*NPIX + n];
        #pragma unroll
        for (int j = 0; j < 8; j++) kv[j] = kb[j*NPIX + n];
        #pragma unroll
        for (int c2 = 0; c2 < 4; c2++) {
            qs[c2] += qv[c2]*qv[c2];
            #pragma unroll
            for (int d = 0; d < 8; d++) S[c2*8 + d] += qv[c2]*kv[d];
        }
        #pragma unroll
        for (int d = 0; d < 8; d++) ks[d] += kv[d]*kv[d];
    }

    __shared__ float s_red[80*8];
    const int lane = tid & 31, wrp = tid >> 5;

    // S entries: global index = i + 32*parity. Reduce within parity group.
    #pragma unroll
    for (int i = 0; i < 32; i++) {
        float v = S[i];
        #pragma unroll
        for (int o = 2; o <= 16; o <<= 1) v += __shfl_xor_sync(0xffffffffu, v, o);
        if (lane < 2) s_red[(i + 32*lane)*8 + wrp] = v;
    }
    // qs entries: global = 64 + 4*parity + i
    #pragma unroll
    for (int i = 0; i < 4; i++) {
        float v = qs[i];
        #pragma unroll
        for (int o = 2; o <= 16; o <<= 1) v += __shfl_xor_sync(0xffffffffu, v, o);
        if (lane < 2) s_red[(64 + 4*lane + i)*8 + wrp] = v;
    }
    // ks: accumulated by BOTH parities -> full reduce counts each pixel twice.
    #pragma unroll
    for (int i = 0; i < 8; i++) {
        float v = ks[i];
        #pragma unroll
        for (int o = 1; o <= 16; o <<= 1) v += __shfl_xor_sync(0xffffffffu, v, o);
        if (lane == 0) s_red[(72 + i)*8 + wrp] = 0.5f*v;
    }
    __syncthreads();
    if (tid < 80) {
        float v = 0.f;
        #pragma unroll
        for (int w = 0; w < 8; w++) v += s_red[tid*8 + w];
        g_part[((b*NHEADS + h)*NCHUNK + chunk)*80 + tid] = v;
    }
}

// ---------------- reduce partials, norms, softmax ------------------------------
__global__ void __launch_bounds__(128) attn_finalize(const float* __restrict__ temp)
{
    const int b = blockIdx.x >> 3, h = blockIdx.x & 7;
    const int tid = threadIdx.x;
    __shared__ float red[80];
    __shared__ float nq[8], nk[8];

    if (tid < 80) {
        float v = 0.f;
        const float* p = g_part + (b*NHEADS + h)*NCHUNK*80 + tid;
        #pragma unroll 8
        for (int ch = 0; ch < NCHUNK; ch++) v += p[ch*80];
        red[tid] = v;
    }
    __syncthreads();
    if (tid < 8)       nq[tid]   = fmaxf(sqrtf(red[64 + tid]),   1e-12f);
    else if (tid < 16) nk[tid-8] = fmaxf(sqrtf(red[72 + tid-8]), 1e-12f);
    __syncthreads();

    if (tid < 64) {
        const int c2 = tid >> 3, d = tid & 7;
        const float logit = red[c2*8 + d] / (nq[c2]*nk[d]) * temp[h];
        float m = logit;
        #pragma unroll
        for (int o = 4; o > 0; o >>= 1) m = fmaxf(m, __shfl_xor_sync(0xffffffffu, m, o, 8));
        const float e = expf(logit - m);
        float s = e;
        #pragma unroll
        for (int o = 4; o > 0; o >>= 1) s += __shfl_xor_sync(0xffffffffu, s, o, 8);
        g_attn[(b*NHEADS + h)*64 + tid] = e / s;
    }
}

// ---------------- W_eff[b] = proj_w @ blockdiag(attn[b]) ----------------------
__global__ void __launch_bounds__(256) compute_weff(const float* __restrict__ proj_w)
{
    const int b = blockIdx.x;
    __shared__ float s_attn[NHEADS*64];
    __shared__ float s_proj[C*C];
    const int tid = threadIdx.x;
    for (int i = tid; i < NHEADS*64; i += 256) s_attn[i] = g_attn[b*NHEADS*64 + i];
    for (int i = tid; i < C*C; i += 256)       s_proj[i] = proj_w[i];
    __syncthreads();
    for (int t = tid; t < C*C; t += 256) {
        const int co = t >> 6, cv = t & 63, hh = cv >> 3, d = cv & 7;
        float acc = 0.f;
        #pragma unroll
        for (int cp = 0; cp < 8; cp++)
            acc += s_proj[co*64 + hh*8 + cp] * s_attn[hh*64 + cp*8 + d];
        g_weff[b*C*C + t] = acc;
    }
}

// ---------------- out = W_eff[b] @ v (fused attn@v + proj conv) ----------------
__global__ void __launch_bounds__(256) apply_out(float* __restrict__ out)
{
    __shared__ unsigned long long s_wp[C*32];
    const int b = blockIdx.y;
    const int tid = threadIdx.x;
    const int n = blockIdx.x*256 + tid;
    const float* wb = g_weff + b*C*C;
    for (int idx = tid; idx < C*32; idx += 256) {
        const int cv = idx >> 5, p = idx & 31;
        s_wp[idx] = pack2(wb[(2*p)*C + cv], wb[(2*p+1)*C + cv]);
    }
    __syncthreads();

    const float* vb = g_V + (size_t)b*(C*NPIX);
    unsigned long long acc[32];
    #pragma unroll
    for (int q = 0; q < 32; q++) acc[q] = 0ULL;
    #pragma unroll 4
    for (int cv = 0; cv < C; cv++) {
        const float v = vb[cv*NPIX + n];
        const unsigned long long vv = pack2(v, v);
        const ulonglong2* wr = (const ulonglong2*)(s_wp + cv*32);
        #pragma unroll
        for (int q = 0; q < 16; q++) {
            const ulonglong2 wq = wr[q];
            FMA2(acc[2*q],   vv, wq.x);
            FMA2(acc[2*q+1], vv, wq.y);
        }
    }
    float* ob = out + (size_t)b*(C*NPIX);
    #pragma unroll
    for (int q = 0; q < 32; q++) {
        float lo, hi; unpack2(acc[q], lo, hi);
        ob[(2*q)*NPIX + n]   = lo;
        ob[(2*q+1)*NPIX + n] = hi;
    }
}

// ---------------- launcher ----------------
extern "C" void kernel_launch(void* const* d_in, const int* in_sizes, int n_in,
                              void* d_out, int out_size)
{
    const float* input1      = (const float*)d_in[0];
    const float* input2      = (const float*)d_in[1];
    const float* q_w         = (const float*)d_in[2];
    const float* q_dw_w      = (const float*)d_in[3];
    const float* kv_w        = (const float*)d_in[4];
    const float* kv_dw_w     = (const float*)d_in[5];
    const float* proj_w      = (const float*)d_in[6];
    const float* temperature = (const float*)d_in[7];
    float* out = (float*)d_out;

    float* mid; cudaGetSymbolAddress((void**)&mid, g_mid);
    float* Q;   cudaGetSymbolAddress((void**)&Q,   g_Q);
    float* K;   cudaGetSymbolAddress((void**)&K,   g_K);
    float* V;   cudaGetSymbolAddress((void**)&V,   g_V);

    dim3 gpix(NPIX/256, BATCH);
    dim3 gdw(WW/32, HH/8, BATCH*C);

    conv1x1_64<<<gpix, 256>>>(input1, q_w, mid);
    dw3x3<<<gdw, 256>>>(mid, q_dw_w, Q);

    conv1x1_64<<<gpix, 256>>>(input2, kv_w, mid);
    dw3x3<<<gdw, 256>>>(mid, kv_dw_w, K);

    conv1x1_64<<<gpix, 256>>>(input2, kv_w + C*C, mid);
    dw3x3<<<gdw, 256>>>(mid, kv_dw_w + C*9, V);

    attn_partial<<<dim3(NCHUNK, NHEADS, BATCH), 256>>>();
    attn_finalize<<<BATCH*NHEADS, 128>>>(temperature);
    compute_weff<<<BATCH, 256>>>(proj_w);
    apply_out<<<dim3(NPIX/256, BATCH), 256>>>(out);
}

// round 3
// speedup vs baseline: 1.6896x; 1.6896x over previous
#include <cuda_runtime.h>
#include <math.h>

#define BATCH 4
#define C 64
#define HH 256
#define WW 256
#define NPIX (HH*WW)
#define NHEADS 8
#define HD 8
#define NCHUNK 64
#define CHUNK (NPIX/NCHUNK)   // 1024

// ---------------- scratch (static device globals; no allocations) ----------------
__device__ float g_mid[BATCH*C*NPIX];
__device__ float g_Q[BATCH*C*NPIX];
__device__ float g_K[BATCH*C*NPIX];
__device__ float g_V[BATCH*C*NPIX];
__device__ float g_part[BATCH*NHEADS*NCHUNK*80];
__device__ float g_attn[BATCH*NHEADS*HD*HD];
__device__ float g_weff[BATCH*C*C];

// ---------------- packed f32x2 helpers ----------------
__device__ __forceinline__ unsigned long long pack2(float lo, float hi) {
    unsigned long long r;
    asm("mov.b64 %0, {%1,%2};" : "=l"(r)
        : "r"(__float_as_uint(lo)), "r"(__float_as_uint(hi)));
    return r;
}
__device__ __forceinline__ void unpack2(unsigned long long p, float& lo, float& hi) {
    unsigned int a, b;
    asm("mov.b64 {%0,%1}, %2;" : "=r"(a), "=r"(b) : "l"(p));
    lo = __uint_as_float(a); hi = __uint_as_float(b);
}
#define FMA2(acc, a, b) \
    asm("fma.rn.f32x2 %0, %1, %2, %0;" : "+l"(acc) : "l"(a), "l"(b))

// ---------------- gemm64: out[co][pix] = sum_ci w[co*64+ci] * in[ci][pix] -----
// 256 threads = 64 pixel-slots x 4 output-groups. Each thread: 4 consecutive
// pixels (float4 LDG/STG) x 16 output channels. Inner loop per ci:
// 1 LDG.128 + 4 LDS.128 (broadcast) + 32 FFMA2 -> FMA-pipe bound.
__global__ void __launch_bounds__(256, 2) gemm64(
    const float* __restrict__ in, const float* __restrict__ w,
    float* __restrict__ out, int w_per_batch)
{
    __shared__ unsigned long long s_wp[C*32];   // [ci][pair p] = (w[2p][ci], w[2p+1][ci])
    const int tid = threadIdx.x;
    const int b = blockIdx.y;
    const int g = tid >> 6;          // output group: channels 16g..16g+15
    const int slot = tid & 63;       // pixel slot
    const int nbase = blockIdx.x*256 + slot*4;

    const float* wb = w + (w_per_batch ? b*C*C : 0);
    for (int idx = tid; idx < C*32; idx += 256) {
        const int ci = idx >> 5, p = idx & 31;
        s_wp[idx] = pack2(wb[(2*p)*C + ci], wb[(2*p+1)*C + ci]);
    }
    __syncthreads();

    const float* ib = in + (size_t)b*(C*NPIX);
    unsigned long long acc[4][8];
    #pragma unroll
    for (int px = 0; px < 4; px++)
        #pragma unroll
        for (int p = 0; p < 8; p++) acc[px][p] = 0ULL;

    const ulonglong2* wg = (const ulonglong2*)(s_wp + g*8);  // group's 8 pairs
    #pragma unroll 4
    for (int ci = 0; ci < C; ci++) {
        const float4 v = *(const float4*)(ib + ci*NPIX + nbase);
        const ulonglong2 w01 = wg[ci*16 + 0];   // (ci*32 + g*8) u64 = ci*16 ull2
        const ulonglong2 w23 = wg[ci*16 + 1];
        const ulonglong2 w45 = wg[ci*16 + 2];
        const ulonglong2 w67 = wg[ci*16 + 3];
        const unsigned long long wp[8] = {w01.x, w01.y, w23.x, w23.y,
                                          w45.x, w45.y, w67.x, w67.y};
        const float vv[4] = {v.x, v.y, v.z, v.w};
        #pragma unroll
        for (int px = 0; px < 4; px++) {
            const unsigned long long vp = pack2(vv[px], vv[px]);
            #pragma unroll
            for (int p = 0; p < 8; p++) FMA2(acc[px][p], vp, wp[p]);
        }
    }

    float* ob = out + (size_t)b*(C*NPIX);
    #pragma unroll
    for (int p = 0; p < 8; p++) {
        float lo0, hi0, lo1, hi1, lo2, hi2, lo3, hi3;
        unpack2(acc[0][p], lo0, hi0); unpack2(acc[1][p], lo1, hi1);
        unpack2(acc[2][p], lo2, hi2); unpack2(acc[3][p], lo3, hi3);
        const int c0 = g*16 + 2*p;
        *(float4*)(ob + (size_t)c0*NPIX + nbase)     = make_float4(lo0, lo1, lo2, lo3);
        *(float4*)(ob + (size_t)(c0+1)*NPIX + nbase) = make_float4(hi0, hi1, hi2, hi3);
    }
}

// ---------------- depthwise 3x3, pad=1, 4 outputs/thread ----------------------
// block 256 = 64 x-groups x 4 rows; grid (1, HH/4, BATCH*C).
__global__ void __launch_bounds__(256) dw3x3(
    const float* __restrict__ in, const float* __restrict__ w,
    float* __restrict__ out)
{
    const int z = blockIdx.z;                       // b*C + c
    const float* ib = in + (size_t)z*NPIX;
    float* ob = out + (size_t)z*NPIX;
    const float* wc = w + (z & (C-1))*9;

    const int tid = threadIdx.x;
    const int x4 = (tid & 63)*4;
    const int y  = blockIdx.y*4 + (tid >> 6);

    float wr[9];
    #pragma unroll
    for (int i = 0; i < 9; i++) wr[i] = __ldg(wc + i);

    float a0 = 0.f, a1 = 0.f, a2 = 0.f, a3 = 0.f;
    #pragma unroll
    for (int dy = -1; dy <= 1; dy++) {
        const int yy = y + dy;
        if (yy < 0 || yy >= HH) continue;
        const float* row = ib + yy*WW;
        const float4 m = *(const float4*)(row + x4);
        const float l = (x4 > 0)        ? __ldg(row + x4 - 1) : 0.f;
        const float r = (x4 + 4 < WW)   ? __ldg(row + x4 + 4) : 0.f;
        const float w0 = wr[(dy+1)*3], w1 = wr[(dy+1)*3+1], w2 = wr[(dy+1)*3+2];
        a0 += w0*l   + w1*m.x + w2*m.y;
        a1 += w0*m.x + w1*m.y + w2*m.z;
        a2 += w0*m.y + w1*m.z + w2*m.w;
        a3 += w0*m.z + w1*m.w + w2*r;
    }
    *(float4*)(ob + y*WW + x4) = make_float4(a0, a1, a2, a3);
}

// ---------------- attn partial: q.k dots + sum-of-squares ---------------------
__global__ void __launch_bounds__(256) attn_partial()
{
    const int chunk = blockIdx.x, h = blockIdx.y, b = blockIdx.z;
    const int tid = threadIdx.x;
    const int parity = tid & 1, slot = tid >> 1;
    const float* qb = g_Q + (size_t)(b*C + h*HD) * NPIX + parity*4*NPIX;
    const float* kb = g_K + (size_t)(b*C + h*HD) * NPIX;

    float S[32], qs[4], ks[8];
    #pragma unroll
    for (int i = 0; i < 32; i++) S[i] = 0.f;
    #pragma unroll
    for (int i = 0; i < 4; i++) qs[i] = 0.f;
    #pragma unroll
    for (int i = 0; i < 8; i++) ks[i] = 0.f;

    const int n0 = chunk * CHUNK;
    #pragma unroll 2
    for (int it = 0; it < CHUNK/128; it++) {
        const int n = n0 + it*128 + slot;
        float qv[4], kv[8];
        #pragma unroll
        for (int j = 0; j < 4; j++) qv[j] = qb[j*NPIX + n];
        #pragma unroll
        for (int j = 0; j < 8; j++) kv[j] = kb[j*NPIX + n];
        #pragma unroll
        for (int c2 = 0; c2 < 4; c2++) {
            qs[c2] += qv[c2]*qv[c2];
            #pragma unroll
            for (int d = 0; d < 8; d++) S[c2*8 + d] += qv[c2]*kv[d];
        }
        #pragma unroll
        for (int d = 0; d < 8; d++) ks[d] += kv[d]*kv[d];
    }

    __shared__ float s_red[80*8];
    const int lane = tid & 31, wrp = tid >> 5;
    #pragma unroll
    for (int i = 0; i < 32; i++) {
        float v = S[i];
        #pragma unroll
        for (int o = 2; o <= 16; o <<= 1) v += __shfl_xor_sync(0xffffffffu, v, o);
        if (lane < 2) s_red[(i + 32*lane)*8 + wrp] = v;
    }
    #pragma unroll
    for (int i = 0; i < 4; i++) {
        float v = qs[i];
        #pragma unroll
        for (int o = 2; o <= 16; o <<= 1) v += __shfl_xor_sync(0xffffffffu, v, o);
        if (lane < 2) s_red[(64 + 4*lane + i)*8 + wrp] = v;
    }
    #pragma unroll
    for (int i = 0; i < 8; i++) {
        float v = ks[i];
        #pragma unroll
        for (int o = 1; o <= 16; o <<= 1) v += __shfl_xor_sync(0xffffffffu, v, o);
        if (lane == 0) s_red[(72 + i)*8 + wrp] = 0.5f*v;
    }
    __syncthreads();
    if (tid < 80) {
        float v = 0.f;
        #pragma unroll
        for (int w = 0; w < 8; w++) v += s_red[tid*8 + w];
        g_part[((b*NHEADS + h)*NCHUNK + chunk)*80 + tid] = v;
    }
}

// ---------------- reduce partials, norms, softmax ------------------------------
__global__ void __launch_bounds__(128) attn_finalize(const float* __restrict__ temp)
{
    const int b = blockIdx.x >> 3, h = blockIdx.x & 7;
    const int tid = threadIdx.x;
    __shared__ float red[80];
    __shared__ float nq[8], nk[8];

    if (tid < 80) {
        float v = 0.f;
        const float* p = g_part + (b*NHEADS + h)*NCHUNK*80 + tid;
        #pragma unroll 8
        for (int ch = 0; ch < NCHUNK; ch++) v += p[ch*80];
        red[tid] = v;
    }
    __syncthreads();
    if (tid < 8)       nq[tid]   = fmaxf(sqrtf(red[64 + tid]),   1e-12f);
    else if (tid < 16) nk[tid-8] = fmaxf(sqrtf(red[72 + tid-8]), 1e-12f);
    __syncthreads();

    if (tid < 64) {
        const int c2 = tid >> 3, d = tid & 7;
        const float logit = red[c2*8 + d] / (nq[c2]*nk[d]) * temp[h];
        float m = logit;
        #pragma unroll
        for (int o = 4; o > 0; o >>= 1) m = fmaxf(m, __shfl_xor_sync(0xffffffffu, m, o, 8));
        const float e = expf(logit - m);
        float s = e;
        #pragma unroll
        for (int o = 4; o > 0; o >>= 1) s += __shfl_xor_sync(0xffffffffu, s, o, 8);
        g_attn[(b*NHEADS + h)*64 + tid] = e / s;
    }
}

// ---------------- W_eff[b] = proj_w @ blockdiag(attn[b]) ----------------------
__global__ void __launch_bounds__(256) compute_weff(const float* __restrict__ proj_w)
{
    const int b = blockIdx.x;
    __shared__ float s_attn[NHEADS*64];
    __shared__ float s_proj[C*C];
    const int tid = threadIdx.x;
    for (int i = tid; i < NHEADS*64; i += 256) s_attn[i] = g_attn[b*NHEADS*64 + i];
    for (int i = tid; i < C*C; i += 256)       s_proj[i] = proj_w[i];
    __syncthreads();
    for (int t = tid; t < C*C; t += 256) {
        const int co = t >> 6, cv = t & 63, hh = cv >> 3, d = cv & 7;
        float acc = 0.f;
        #pragma unroll
        for (int cp = 0; cp < 8; cp++)
            acc += s_proj[co*64 + hh*8 + cp] * s_attn[hh*64 + cp*8 + d];
        g_weff[b*C*C + t] = acc;
    }
}

// ---------------- launcher ----------------
extern "C" void kernel_launch(void* const* d_in, const int* in_sizes, int n_in,
                              void* d_out, int out_size)
{
    const float* input1      = (const float*)d_in[0];
    const float* input2      = (const float*)d_in[1];
    const float* q_w         = (const float*)d_in[2];
    const float* q_dw_w      = (const float*)d_in[3];
    const float* kv_w        = (const float*)d_in[4];
    const float* kv_dw_w     = (const float*)d_in[5];
    const float* proj_w      = (const float*)d_in[6];
    const float* temperature = (const float*)d_in[7];
    float* out = (float*)d_out;

    float* mid; cudaGetSymbolAddress((void**)&mid, g_mid);
    float* Q;   cudaGetSymbolAddress((void**)&Q,   g_Q);
    float* K;   cudaGetSymbolAddress((void**)&K,   g_K);
    float* V;   cudaGetSymbolAddress((void**)&V,   g_V);
    float* Weff; cudaGetSymbolAddress((void**)&Weff, g_weff);

    dim3 gpix(NPIX/256, BATCH);
    dim3 gdw(1, HH/4, BATCH*C);

    gemm64<<<gpix, 256>>>(input1, q_w, mid, 0);
    dw3x3<<<gdw, 256>>>(mid, q_dw_w, Q);

    gemm64<<<gpix, 256>>>(input2, kv_w, mid, 0);
    dw3x3<<<gdw, 256>>>(mid, kv_dw_w, K);

    gemm64<<<gpix, 256>>>(input2, kv_w + C*C, mid, 0);
    dw3x3<<<gdw, 256>>>(mid, kv_dw_w + C*9, V);

    attn_partial<<<dim3(NCHUNK, NHEADS, BATCH), 256>>>();
    attn_finalize<<<BATCH*NHEADS, 128>>>(temperature);
    compute_weff<<<BATCH, 256>>>(proj_w);
    gemm64<<<gpix, 256>>>(V, Weff, out, 1);
}

// round 5
// speedup vs baseline: 2.1147x; 1.2516x over previous
#include <cuda_runtime.h>
#include <math.h>
#include <stdint.h>

#define BATCH 4
#define C 64
#define HH 256
#define WW 256
#define NPIX (HH*WW)
#define NHEADS 8
#define NCHUNK 64
#define CHUNK (NPIX/NCHUNK)   // 1024
#define PITCH 136             // smem row pitch (floats): conflict-free B-frag LDS

// ---------------- scratch (static device globals) ----------------
__device__ float g_mid[BATCH*C*NPIX];
__device__ float g_Q[BATCH*C*NPIX];
__device__ float g_K[BATCH*C*NPIX];
__device__ float g_V[BATCH*C*NPIX];
__device__ float g_part[BATCH*NHEADS*NCHUNK*80];
__device__ float g_attn[BATCH*NHEADS*64];
__device__ float g_weff[BATCH*C*C];

__device__ __forceinline__ uint32_t f2tf32(float v){
    uint32_t t; asm("cvt.rna.tf32.f32 %0, %1;" : "=r"(t) : "f"(v)); return t;
}

#define MMA_TF32(c0,c1,c2,c3,a0,a1,a2,a3,b0,b1) \
  asm volatile("mma.sync.aligned.m16n8k8.row.col.f32.tf32.tf32.f32 " \
    "{%0,%1,%2,%3}, {%4,%5,%6,%7}, {%8,%9}, {%0,%1,%2,%3};" \
    : "+f"(c0),"+f"(c1),"+f"(c2),"+f"(c3) \
    : "r"(a0),"r"(a1),"r"(a2),"r"(a3),"r"(b0),"r"(b1))

// ============ gemm_mma: out[co][px] = sum_ci w[co][ci] * in[ci][px] ============
// 128 threads = 4 warps; warp w owns co-tile [16w,16w+16). CTA tile = 128 px.
// A (weights) in registers as 3xTF32 hi/lo fragments; X staged hi/lo in smem.
__global__ void __launch_bounds__(128) gemm_mma(
    const float* __restrict__ in, const float* __restrict__ w,
    float* __restrict__ out, int w_per_batch)
{
    extern __shared__ float sm[];              // [2][64][PITCH]
    float* s_hi = sm;
    float* s_lo = sm + 64*PITCH;

    const int tid  = threadIdx.x;
    const int lane = tid & 31, warp = tid >> 5;
    const int b    = blockIdx.y;
    const int px0  = blockIdx.x * 128;
    const int gid  = lane >> 2, tig = lane & 3;

    // ---- weight fragments: A[16 co][64 ci], hi/lo split ----
    const float* wb = w + (w_per_batch ? b*C*C : 0);
    uint32_t Ah[8][4], Al[8][4];
    const int co_r0 = warp*16 + gid;
    #pragma unroll
    for (int kc = 0; kc < 8; kc++) {
        #pragma unroll
        for (int j = 0; j < 4; j++) {
            const int row = co_r0 + (j & 1)*8;
            const int col = kc*8 + tig + (j >> 1)*4;
            const float x = __ldg(wb + row*C + col);
            const uint32_t h = f2tf32(x);
            Ah[kc][j] = h;
            Al[kc][j] = f2tf32(x - __uint_as_float(h));
        }
    }

    // ---- stage X tile: in[ci][px0..px0+127] -> s_hi/s_lo (tf32 split) ----
    const float* ib = in + (size_t)b*(C*NPIX) + px0;
    #pragma unroll
    for (int i = 0; i < 16; i++) {
        const int ci = warp + 4*i;                 // warp-constant row
        const float4 v = *(const float4*)(ib + (size_t)ci*NPIX + lane*4);
        uint32_t h0 = f2tf32(v.x), h1 = f2tf32(v.y);
        uint32_t h2 = f2tf32(v.z), h3 = f2tf32(v.w);
        uint32_t l0 = f2tf32(v.x - __uint_as_float(h0));
        uint32_t l1 = f2tf32(v.y - __uint_as_float(h1));
        uint32_t l2 = f2tf32(v.z - __uint_as_float(h2));
        uint32_t l3 = f2tf32(v.w - __uint_as_float(h3));
        *(uint4*)(s_hi + ci*PITCH + lane*4) = make_uint4(h0, h1, h2, h3);
        *(uint4*)(s_lo + ci*PITCH + lane*4) = make_uint4(l0, l1, l2, l3);
    }
    __syncthreads();

    // ---- compute: 16 n-tiles of 8 px each ----
    float* ob = out + (size_t)b*(C*NPIX) + px0;
    const int co_base = warp*16;
    #pragma unroll 2
    for (int nt = 0; nt < 16; nt++) {
        float c0 = 0.f, c1 = 0.f, c2 = 0.f, c3 = 0.f;
        const int pxl = nt*8 + gid;
        #pragma unroll
        for (int kc = 0; kc < 8; kc++) {
            const int r0 = (kc*8 + tig)*PITCH + pxl;
            const int r1 = r0 + 4*PITCH;
            const uint32_t b0h = __float_as_uint(s_hi[r0]);
            const uint32_t b1h = __float_as_uint(s_hi[r1]);
            const uint32_t b0l = __float_as_uint(s_lo[r0]);
            const uint32_t b1l = __float_as_uint(s_lo[r1]);
            MMA_TF32(c0,c1,c2,c3, Ah[kc][0],Ah[kc][1],Ah[kc][2],Ah[kc][3], b0h,b1h);
            MMA_TF32(c0,c1,c2,c3, Ah[kc][0],Ah[kc][1],Ah[kc][2],Ah[kc][3], b0l,b1l);
            MMA_TF32(c0,c1,c2,c3, Al[kc][0],Al[kc][1],Al[kc][2],Al[kc][3], b0h,b1h);
        }
        const int pxs = nt*8 + tig*2;
        *(float2*)(ob + (size_t)(co_base+gid  )*NPIX + pxs) = make_float2(c0, c1);
        *(float2*)(ob + (size_t)(co_base+gid+8)*NPIX + pxs) = make_float2(c2, c3);
    }
}

// ---------------- depthwise 3x3, pad=1, 4 outputs/thread ----------------------
__global__ void __launch_bounds__(256) dw3x3(
    const float* __restrict__ in, const float* __restrict__ w,
    float* __restrict__ out)
{
    const int z = blockIdx.z;
    const float* ib = in + (size_t)z*NPIX;
    float* ob = out + (size_t)z*NPIX;
    const float* wc = w + (z & (C-1))*9;

    const int tid = threadIdx.x;
    const int x4 = (tid & 63)*4;
    const int y  = blockIdx.y*4 + (tid >> 6);

    float wr[9];
    #pragma unroll
    for (int i = 0; i < 9; i++) wr[i] = __ldg(wc + i);

    float a0 = 0.f, a1 = 0.f, a2 = 0.f, a3 = 0.f;
    #pragma unroll
    for (int dy = -1; dy <= 1; dy++) {
        const int yy = y + dy;
        if (yy < 0 || yy >= HH) continue;
        const float* row = ib + yy*WW;
        const float4 m = *(const float4*)(row + x4);
        const float l = (x4 > 0)      ? __ldg(row + x4 - 1) : 0.f;
        const float r = (x4 + 4 < WW) ? __ldg(row + x4 + 4) : 0.f;
        const float w0 = wr[(dy+1)*3], w1 = wr[(dy+1)*3+1], w2 = wr[(dy+1)*3+2];
        a0 += w0*l   + w1*m.x + w2*m.y;
        a1 += w0*m.x + w1*m.y + w2*m.z;
        a2 += w0*m.y + w1*m.z + w2*m.w;
        a3 += w0*m.z + w1*m.w + w2*r;
    }
    *(float4*)(ob + y*WW + x4) = make_float4(a0, a1, a2, a3);
}

// ---------------- attn partial: q.k dots + sum-of-squares ---------------------
__global__ void __launch_bounds__(256) attn_partial()
{
    const int chunk = blockIdx.x, h = blockIdx.y, b = blockIdx.z;
    const int tid = threadIdx.x;
    const int parity = tid & 1, slot = tid >> 1;
    const float* qb = g_Q + (size_t)(b*C + h*8) * NPIX + parity*4*NPIX;
    const float* kb = g_K + (size_t)(b*C + h*8) * NPIX;

    float S[32], qs[4], ks[8];
    #pragma unroll
    for (int i = 0; i < 32; i++) S[i] = 0.f;
    #pragma unroll
    for (int i = 0; i < 4; i++) qs[i] = 0.f;
    #pragma unroll
    for (int i = 0; i < 8; i++) ks[i] = 0.f;

    const int n0 = chunk * CHUNK;
    #pragma unroll 2
    for (int it = 0; it < CHUNK/128; it++) {
        const int n = n0 + it*128 + slot;
        float qv[4], kv[8];
        #pragma unroll
        for (int j = 0; j < 4; j++) qv[j] = qb[j*NPIX + n];
        #pragma unroll
        for (int j = 0; j < 8; j++) kv[j] = kb[j*NPIX + n];
        #pragma unroll
        for (int c2 = 0; c2 < 4; c2++) {
            qs[c2] += qv[c2]*qv[c2];
            #pragma unroll
            for (int d = 0; d < 8; d++) S[c2*8 + d] += qv[c2]*kv[d];
        }
        #pragma unroll
        for (int d = 0; d < 8; d++) ks[d] += kv[d]*kv[d];
    }

    __shared__ float s_red[80*8];
    const int lane = tid & 31, wrp = tid >> 5;
    #pragma unroll
    for (int i = 0; i < 32; i++) {
        float v = S[i];
        #pragma unroll
        for (int o = 2; o <= 16; o <<= 1) v += __shfl_xor_sync(0xffffffffu, v, o);
        if (lane < 2) s_red[(i + 32*lane)*8 + wrp] = v;
    }
    #pragma unroll
    for (int i = 0; i < 4; i++) {
        float v = qs[i];
        #pragma unroll
        for (int o = 2; o <= 16; o <<= 1) v += __shfl_xor_sync(0xffffffffu, v, o);
        if (lane < 2) s_red[(64 + 4*lane + i)*8 + wrp] = v;
    }
    #pragma unroll
    for (int i = 0; i < 8; i++) {
        float v = ks[i];
        #pragma unroll
        for (int o = 1; o <= 16; o <<= 1) v += __shfl_xor_sync(0xffffffffu, v, o);
        if (lane == 0) s_red[(72 + i)*8 + wrp] = 0.5f*v;
    }
    __syncthreads();
    if (tid < 80) {
        float v = 0.f;
        #pragma unroll
        for (int w = 0; w < 8; w++) v += s_red[tid*8 + w];
        g_part[((b*NHEADS + h)*NCHUNK + chunk)*80 + tid] = v;
    }
}

// ---------------- reduce partials, norms, softmax ------------------------------
__global__ void __launch_bounds__(128) attn_finalize(const float* __restrict__ temp)
{
    const int b = blockIdx.x >> 3, h = blockIdx.x & 7;
    const int tid = threadIdx.x;
    __shared__ float red[80];
    __shared__ float nq[8], nk[8];

    if (tid < 80) {
        float v = 0.f;
        const float* p = g_part + (b*NHEADS + h)*NCHUNK*80 + tid;
        #pragma unroll 8
        for (int ch = 0; ch < NCHUNK; ch++) v += p[ch*80];
        red[tid] = v;
    }
    __syncthreads();
    if (tid < 8)       nq[tid]   = fmaxf(sqrtf(red[64 + tid]),   1e-12f);
    else if (tid < 16) nk[tid-8] = fmaxf(sqrtf(red[72 + tid-8]), 1e-12f);
    __syncthreads();

    if (tid < 64) {
        const int c2 = tid >> 3, d = tid & 7;
        const float logit = red[c2*8 + d] / (nq[c2]*nk[d]) * temp[h];
        float m = logit;
        #pragma unroll
        for (int o = 4; o > 0; o >>= 1) m = fmaxf(m, __shfl_xor_sync(0xffffffffu, m, o, 8));
        const float e = expf(logit - m);
        float s = e;
        #pragma unroll
        for (int o = 4; o > 0; o >>= 1) s += __shfl_xor_sync(0xffffffffu, s, o, 8);
        g_attn[(b*NHEADS + h)*64 + tid] = e / s;
    }
}

// ---------------- W_eff[b] = proj_w @ blockdiag(attn[b]) ----------------------
__global__ void __launch_bounds__(256) compute_weff(const float* __restrict__ proj_w)
{
    const int b = blockIdx.x;
    __shared__ float s_attn[NHEADS*64];
    __shared__ float s_proj[C*C];
    const int tid = threadIdx.x;
    for (int i = tid; i < NHEADS*64; i += 256) s_attn[i] = g_attn[b*NHEADS*64 + i];
    for (int i = tid; i < C*C; i += 256)       s_proj[i] = proj_w[i];
    __syncthreads();
    for (int t = tid; t < C*C; t += 256) {
        const int co = t >> 6, cv = t & 63, hh = cv >> 3, d = cv & 7;
        float acc = 0.f;
        #pragma unroll
        for (int cp = 0; cp < 8; cp++)
            acc += s_proj[co*64 + hh*8 + cp] * s_attn[hh*64 + cp*8 + d];
        g_weff[b*C*C + t] = acc;
    }
}

// ---------------- launcher ----------------
extern "C" void kernel_launch(void* const* d_in, const int* in_sizes, int n_in,
                              void* d_out, int out_size)
{
    const float* input1      = (const float*)d_in[0];
    const float* input2      = (const float*)d_in[1];
    const float* q_w         = (const float*)d_in[2];
    const float* q_dw_w      = (const float*)d_in[3];
    const float* kv_w        = (const float*)d_in[4];
    const float* kv_dw_w     = (const float*)d_in[5];
    const float* proj_w      = (const float*)d_in[6];
    const float* temperature = (const float*)d_in[7];
    float* out = (float*)d_out;

    float* mid;  cudaGetSymbolAddress((void**)&mid,  g_mid);
    float* Q;    cudaGetSymbolAddress((void**)&Q,    g_Q);
    float* K;    cudaGetSymbolAddress((void**)&K,    g_K);
    float* V;    cudaGetSymbolAddress((void**)&V,    g_V);
    float* Weff; cudaGetSymbolAddress((void**)&Weff, g_weff);

    const int SMEM = 2 * 64 * PITCH * 4;   // 69632 B
    cudaFuncSetAttribute(gemm_mma, cudaFuncAttributeMaxDynamicSharedMemorySize, SMEM);

    dim3 ggemm(NPIX/128, BATCH);          // (512, 4)
    dim3 gdw(1, HH/4, BATCH*C);

    // order: launch #6 (ncu -s 5 -c 1 target) is a gemm_mma
    gemm_mma<<<ggemm, 128, SMEM>>>(input1, q_w, mid, 0);          // 1
    dw3x3<<<gdw, 256>>>(mid, q_dw_w, Q);                          // 2
    gemm_mma<<<ggemm, 128, SMEM>>>(input2, kv_w, mid, 0);         // 3
    dw3x3<<<gdw, 256>>>(mid, kv_dw_w, K);                         // 4
    attn_partial<<<dim3(NCHUNK, NHEADS, BATCH), 256>>>();         // 5
    gemm_mma<<<ggemm, 128, SMEM>>>(input2, kv_w + C*C, mid, 0);   // 6 <- profiled
    dw3x3<<<gdw, 256>>>(mid, kv_dw_w + C*9, V);                   // 7
    attn_finalize<<<BATCH*NHEADS, 128>>>(temperature);            // 8
    compute_weff<<<BATCH, 256>>>(proj_w);                         // 9
    gemm_mma<<<ggemm, 128, SMEM>>>(V, Weff, out, 1);              // 10
}